// round 6
// baseline (speedup 1.0000x reference)
#include <cuda_runtime.h>
#include <cstdint>

#define FDIM   1024
#define FV     256            // float4 per row
#define DDOM   8
#define MAXN   16384
#define RSB    64             // rows per stats segment
#define MAXSEG (MAXN / RSB)   // 256 segments
#define RA     8              // rows per apply block
#define EPSV   1e-5f

// ---------------- scratch ----------------
__device__ float g_P[MAXSEG * DDOM * FDIM];   // partial sum(x)   per (seg, d)
__device__ float g_Q[MAXSEG * DDOM * FDIM];   // partial sum(x*x) per (seg, d)
__device__ int   g_c[MAXSEG * DDOM];          // per-seg domain counts
__device__ unsigned char g_ydom[MAXN];        // decoded domain per row
__device__ float g_A[DDOM * FDIM];            // gamma * inv
__device__ float g_B[DDOM * FDIM];            // beta - mean * gamma * inv

// int64-vs-int32 y detection (odd 32-bit words all zero over 32 values)
__device__ __forceinline__ int detect64(const int* __restrict__ y) {
    const int4* p = (const int4*)y;
    int acc = 0;
#pragma unroll
    for (int i = 0; i < 8; i++) { int4 a = p[i]; acc |= a.y | a.w; }
    return acc == 0;
}

#define ACCUM(v)                                        \
    s1.x += v.x; s1.y += v.y; s1.z += v.z; s1.w += v.w; \
    s2.x = fmaf(v.x, v.x, s2.x);                        \
    s2.y = fmaf(v.y, v.y, s2.y);                        \
    s2.z = fmaf(v.z, v.z, s2.z);                        \
    s2.w = fmaf(v.w, v.w, s2.w);

// ---- K1: stats. 512 threads: 2 row-parity subs x 256 f4 positions. ----
__global__ __launch_bounds__(512, 2)
void stats_k(const float4* __restrict__ x4, const int* __restrict__ yi, int n) {
    __shared__ int lst[DDOM][RSB];    // prescaled row offsets (row * FV)
    __shared__ int cnt[DDOM];
    __shared__ float4 sm1[FV];        // sub1 -> sub0 reduction buffers
    __shared__ float4 sm2[FV];
    const int tid  = threadIdx.x;
    const int pos  = tid & 255;       // f4 position within row
    const int sub  = tid >> 8;        // row-parity sub (0/1)
    const int base = blockIdx.x * RSB;

    if (tid < DDOM) cnt[tid] = 0;
    __syncthreads();

    if (tid < 32) {                   // warp 0: deterministic concat sort
        const int is64 = detect64(yi);
        {   // tile 0
            const int r = base + tid;
            int d = -1;
            if (r < n) d = is64 ? yi[2 * r] : yi[r];
            unsigned m = __match_any_sync(0xffffffffu, d);
            int rank = __popc(m & ((1u << tid) - 1u));
            if (d >= 0) {
                g_ydom[r] = (unsigned char)d;
                lst[d][rank] = r * FV;
                if (rank == 0) cnt[d] = __popc(m);
            }
        }
        __syncwarp();
        {   // tile 1 (append)
            const int r = base + 32 + tid;
            int d = -1;
            if (r < n) d = is64 ? yi[2 * r] : yi[r];
            unsigned m = __match_any_sync(0xffffffffu, d);
            int rank = __popc(m & ((1u << tid) - 1u));
            int off = (d >= 0) ? cnt[d] : 0;
            __syncwarp();
            if (d >= 0) {
                g_ydom[r] = (unsigned char)d;
                lst[d][off + rank] = r * FV;
                if (rank == 0) cnt[d] = off + __popc(m);
            }
        }
    }
    __syncthreads();

#pragma unroll
    for (int d = 0; d < DDOM; d++) {
        const int nd = cnt[d];
        float4 s1 = make_float4(0.f, 0.f, 0.f, 0.f);
        float4 s2 = make_float4(0.f, 0.f, 0.f, 0.f);
        int i = sub;                  // sub0: even entries, sub1: odd
        for (; i + 6 < nd; i += 8) {
            float4 v0 = __ldcg(x4 + lst[d][i]     + pos);
            float4 v1 = __ldcg(x4 + lst[d][i + 2] + pos);
            float4 v2 = __ldcg(x4 + lst[d][i + 4] + pos);
            float4 v3 = __ldcg(x4 + lst[d][i + 6] + pos);
            ACCUM(v0); ACCUM(v1); ACCUM(v2); ACCUM(v3);
        }
        for (; i < nd; i += 2) {
            float4 v = __ldcg(x4 + lst[d][i] + pos);
            ACCUM(v);
        }
        // combine subs via smem, sub0 writes partial
        if (sub) { sm1[pos] = s1; sm2[pos] = s2; }
        __syncthreads();
        if (!sub) {
            float4 t1 = sm1[pos], t2 = sm2[pos];
            s1.x += t1.x; s1.y += t1.y; s1.z += t1.z; s1.w += t1.w;
            s2.x += t2.x; s2.y += t2.y; s2.z += t2.z; s2.w += t2.w;
            const size_t o = ((size_t)blockIdx.x * DDOM + d) * FV + pos;
            ((float4*)g_P)[o] = s1;
            ((float4*)g_Q)[o] = s2;
        }
        __syncthreads();
    }
    if (tid < DDOM) g_c[blockIdx.x * DDOM + tid] = cnt[tid];
}

// ---------------- K2: fold segments -> A/B tables ----------------
__global__ __launch_bounds__(256)
void finalize_k(const float* __restrict__ gamma, const float* __restrict__ beta,
                int nseg) {
    __shared__ int scnt[256];
    const int tid  = threadIdx.x;
    const int d    = blockIdx.x >> 5;
    const int w    = tid >> 5, lane = tid & 31;
    const int posIdx = (blockIdx.x & 31) * 8 + w;   // f4 index 0..255

    {
        int c = 0;
        for (int s = tid; s < nseg; s += 256) c += g_c[s * DDOM + d];
        scnt[tid] = c;
    }
    __syncthreads();
    for (int off = 128; off > 0; off >>= 1) {
        if (tid < off) scnt[tid] += scnt[tid + off];
        __syncthreads();
    }
    const float c = (float)scnt[0];

    const float4* P4 = (const float4*)g_P;
    const float4* Q4 = (const float4*)g_Q;
    float4 ap = make_float4(0.f, 0.f, 0.f, 0.f);
    float4 aq = make_float4(0.f, 0.f, 0.f, 0.f);
    for (int s = lane; s < nseg; s += 32) {
        const size_t o = ((size_t)s * DDOM + d) * FV + posIdx;
        float4 p = P4[o], q = Q4[o];
        ap.x += p.x; ap.y += p.y; ap.z += p.z; ap.w += p.w;
        aq.x += q.x; aq.y += q.y; aq.z += q.z; aq.w += q.w;
    }
#pragma unroll
    for (int off = 16; off > 0; off >>= 1) {
        ap.x += __shfl_down_sync(0xffffffffu, ap.x, off);
        ap.y += __shfl_down_sync(0xffffffffu, ap.y, off);
        ap.z += __shfl_down_sync(0xffffffffu, ap.z, off);
        ap.w += __shfl_down_sync(0xffffffffu, ap.w, off);
        aq.x += __shfl_down_sync(0xffffffffu, aq.x, off);
        aq.y += __shfl_down_sync(0xffffffffu, aq.y, off);
        aq.z += __shfl_down_sync(0xffffffffu, aq.z, off);
        aq.w += __shfl_down_sync(0xffffffffu, aq.w, off);
    }

    if (lane == 0) {
        const int o = d * FDIM + posIdx * 4;
        float4 A, Bv;
        if (c > 1.5f) {
            const float rc = 1.0f / c;
            float4 g  = *(const float4*)(gamma + o);
            float4 be = *(const float4*)(beta + o);
            float mx = ap.x * rc, my = ap.y * rc, mz = ap.z * rc, mw = ap.w * rc;
            float vx = fmaf(-mx, mx, aq.x * rc);
            float vy = fmaf(-my, my, aq.y * rc);
            float vz = fmaf(-mz, mz, aq.z * rc);
            float vw = fmaf(-mw, mw, aq.w * rc);
            A.x = g.x * rsqrtf(vx + EPSV);
            A.y = g.y * rsqrtf(vy + EPSV);
            A.z = g.z * rsqrtf(vz + EPSV);
            A.w = g.w * rsqrtf(vw + EPSV);
            Bv.x = fmaf(-mx, A.x, be.x);
            Bv.y = fmaf(-my, A.y, be.y);
            Bv.z = fmaf(-mz, A.z, be.z);
            Bv.w = fmaf(-mw, A.w, be.w);
        } else if (c > 0.5f) {   // single-sample domain: out = x
            A  = make_float4(1.f, 1.f, 1.f, 1.f);
            Bv = make_float4(0.f, 0.f, 0.f, 0.f);
        } else {                 // empty domain (unused)
            A  = make_float4(0.f, 0.f, 0.f, 0.f);
            Bv = make_float4(0.f, 0.f, 0.f, 0.f);
        }
        *(float4*)(g_A + o) = A;
        *(float4*)(g_B + o) = Bv;
    }
}

// ---------------- K3: out = A[d]*x + B[d] ----------------
__global__ __launch_bounds__(256)
void apply_k(const float4* __restrict__ x4, float4* __restrict__ o4, int n) {
    __shared__ int sd[RA];
    const int tid = threadIdx.x;
    const int r0  = blockIdx.x * RA;

    if (tid < RA) {
        const int r = r0 + tid;
        sd[tid] = (r < n) ? (int)g_ydom[r] : 0;
    }
    __syncthreads();

    const float4* A4 = (const float4*)g_A;
    const float4* B4 = (const float4*)g_B;

#pragma unroll
    for (int j = 0; j < RA; j += 4) {
        const int r = r0 + j;
        if (r + 3 < n) {
            const int d0 = sd[j], d1 = sd[j + 1], d2 = sd[j + 2], d3 = sd[j + 3];
            const float4* p = x4 + (size_t)r * FV + tid;
            float4 v0 = __ldcs(p);
            float4 v1 = __ldcs(p + FV);
            float4 v2 = __ldcs(p + 2 * FV);
            float4 v3 = __ldcs(p + 3 * FV);
            float4 a0 = __ldg(A4 + d0 * FV + tid);
            float4 b0 = __ldg(B4 + d0 * FV + tid);
            float4 a1 = __ldg(A4 + d1 * FV + tid);
            float4 b1 = __ldg(B4 + d1 * FV + tid);
            float4 a2 = __ldg(A4 + d2 * FV + tid);
            float4 b2 = __ldg(B4 + d2 * FV + tid);
            float4 a3 = __ldg(A4 + d3 * FV + tid);
            float4 b3 = __ldg(B4 + d3 * FV + tid);
            float4 w0, w1, w2, w3;
            w0.x = fmaf(v0.x, a0.x, b0.x); w0.y = fmaf(v0.y, a0.y, b0.y);
            w0.z = fmaf(v0.z, a0.z, b0.z); w0.w = fmaf(v0.w, a0.w, b0.w);
            w1.x = fmaf(v1.x, a1.x, b1.x); w1.y = fmaf(v1.y, a1.y, b1.y);
            w1.z = fmaf(v1.z, a1.z, b1.z); w1.w = fmaf(v1.w, a1.w, b1.w);
            w2.x = fmaf(v2.x, a2.x, b2.x); w2.y = fmaf(v2.y, a2.y, b2.y);
            w2.z = fmaf(v2.z, a2.z, b2.z); w2.w = fmaf(v2.w, a2.w, b2.w);
            w3.x = fmaf(v3.x, a3.x, b3.x); w3.y = fmaf(v3.y, a3.y, b3.y);
            w3.z = fmaf(v3.z, a3.z, b3.z); w3.w = fmaf(v3.w, a3.w, b3.w);
            float4* q = o4 + (size_t)r * FV + tid;
            __stcs(q,          w0);
            __stcs(q + FV,     w1);
            __stcs(q + 2 * FV, w2);
            __stcs(q + 3 * FV, w3);
        } else {
            for (int k = 0; k < 4; k++) {
                const int rr = r + k;
                if (rr >= n) break;
                const int dd = sd[j + k];
                float4 v = __ldcs(x4 + (size_t)rr * FV + tid);
                float4 a = __ldg(A4 + dd * FV + tid);
                float4 b = __ldg(B4 + dd * FV + tid);
                float4 w;
                w.x = fmaf(v.x, a.x, b.x); w.y = fmaf(v.y, a.y, b.y);
                w.z = fmaf(v.z, a.z, b.z); w.w = fmaf(v.w, a.w, b.w);
                __stcs(o4 + (size_t)rr * FV + tid, w);
            }
        }
    }
}

extern "C" void kernel_launch(void* const* d_in, const int* in_sizes, int n_in,
                              void* d_out, int out_size) {
    const float* x     = (const float*)d_in[0];
    const int*   y     = (const int*)d_in[1];
    const float* gamma = (const float*)d_in[2];
    const float* beta  = (const float*)d_in[3];
    float* out = (float*)d_out;

    const int n    = in_sizes[1];
    const int nseg = (n + RSB - 1) / RSB;       // 256

    stats_k<<<nseg, 512>>>((const float4*)x, y, n);
    finalize_k<<<DDOM * 32, 256>>>(gamma, beta, nseg);
    apply_k<<<(n + RA - 1) / RA, 256>>>((const float4*)x, (float4*)out, n);
}

// round 7
// speedup vs baseline: 1.2838x; 1.2838x over previous
#include <cuda_runtime.h>
#include <cstdint>

#define FDIM   1024
#define FV     256            // float4 per row
#define DDOM   8
#define MAXN   16384
#define NSEG   296            // stats blocks = 2 full waves on 148 SMs
#define MAXR   64             // max rows per stats block
#define RA     8              // rows per apply block
#define EPSV   1e-5f

// ---------------- scratch ----------------
__device__ float g_P[NSEG * DDOM * FDIM];     // partial sum(x)   per (seg, d)
__device__ float g_Q[NSEG * DDOM * FDIM];     // partial sum(x*x) per (seg, d)
__device__ int   g_c[NSEG * DDOM];            // per-seg domain counts
__device__ unsigned char g_ydom[MAXN];        // decoded domain per row
__device__ float g_A[DDOM * FDIM];            // gamma * inv
__device__ float g_B[DDOM * FDIM];            // beta - mean * gamma * inv

// int64-vs-int32 y detection (odd 32-bit words all zero over 32 values)
__device__ __forceinline__ int detect64(const int* __restrict__ y) {
    const int4* p = (const int4*)y;
    int acc = 0;
#pragma unroll
    for (int i = 0; i < 8; i++) { int4 a = p[i]; acc |= a.y | a.w; }
    return acc == 0;
}

#define ACCUM(v)                                        \
    s1.x += v.x; s1.y += v.y; s1.z += v.z; s1.w += v.w; \
    s2.x = fmaf(v.x, v.x, s2.x);                        \
    s2.y = fmaf(v.y, v.y, s2.y);                        \
    s2.z = fmaf(v.z, v.z, s2.z);                        \
    s2.w = fmaf(v.w, v.w, s2.w);

// ---- K1: stats. 296 blocks x 55/56 rows, concat-sorted, 1 acc pair. ----
__global__ __launch_bounds__(256, 4)
void stats_k(const float4* __restrict__ x4, const int* __restrict__ yi,
             int n, int rlo, int rem) {
    __shared__ int lst[DDOM][MAXR];   // prescaled row offsets (row * FV)
    __shared__ int cnt[DDOM];
    const int tid  = threadIdx.x;
    const int b    = blockIdx.x;
    const int base = b * rlo + min(b, rem);
    const int nrow = rlo + (b < rem ? 1 : 0);
    const int rend = min(base + nrow, n);

    if (tid < DDOM) cnt[tid] = 0;
    __syncthreads();

    if (tid < 32) {                   // warp 0: deterministic concat sort
        const int is64 = detect64(yi);
        for (int t0 = base; t0 < rend; t0 += 32) {
            const int r = t0 + tid;
            int d = -1;
            if (r < rend) d = is64 ? yi[2 * r] : yi[r];
            unsigned m = __match_any_sync(0xffffffffu, d);
            int rank = __popc(m & ((1u << tid) - 1u));
            int off = (d >= 0) ? cnt[d] : 0;   // all lanes read before leaders write
            __syncwarp();
            if (d >= 0) {
                g_ydom[r] = (unsigned char)d;
                lst[d][off + rank] = r * FV;
                if (rank == 0) cnt[d] = off + __popc(m);
            }
            __syncwarp();
        }
    }
    __syncthreads();

#pragma unroll
    for (int d = 0; d < DDOM; d++) {
        const int nd = cnt[d];
        float4 s1 = make_float4(0.f, 0.f, 0.f, 0.f);
        float4 s2 = make_float4(0.f, 0.f, 0.f, 0.f);
        int i = 0;
        for (; i + 4 <= nd; i += 4) {
            float4 v0 = __ldcg(x4 + lst[d][i]     + tid);
            float4 v1 = __ldcg(x4 + lst[d][i + 1] + tid);
            float4 v2 = __ldcg(x4 + lst[d][i + 2] + tid);
            float4 v3 = __ldcg(x4 + lst[d][i + 3] + tid);
            ACCUM(v0); ACCUM(v1); ACCUM(v2); ACCUM(v3);
        }
        for (; i < nd; i++) {
            float4 v = __ldcg(x4 + lst[d][i] + tid);
            ACCUM(v);
        }
        const size_t o = ((size_t)b * DDOM + d) * FV + tid;
        ((float4*)g_P)[o] = s1;
        ((float4*)g_Q)[o] = s2;
    }
    if (tid < DDOM) g_c[b * DDOM + tid] = cnt[tid];
}

// ---- K2: fold segments -> A/B. grid = 8 dom x 8 f4-slices = 64 blocks. ----
// Warp w strides segments; lanes cover 32 consecutive f4 (512B coalesced).
__global__ __launch_bounds__(256)
void finalize_k(const float* __restrict__ gamma, const float* __restrict__ beta,
                int nseg) {
    __shared__ float4 smP[8][32];
    __shared__ float4 smQ[8][32];
    __shared__ int    scnt[256];
    const int tid  = threadIdx.x;
    const int d    = blockIdx.x >> 3;
    const int fs   = blockIdx.x & 7;
    const int w    = tid >> 5, lane = tid & 31;
    const int posIdx = fs * 32 + lane;            // f4 index 0..255

    {   // domain count
        int c = 0;
        for (int s = tid; s < nseg; s += 256) c += g_c[s * DDOM + d];
        scnt[tid] = c;
    }

    const float4* P4 = (const float4*)g_P;
    const float4* Q4 = (const float4*)g_Q;
    float4 ap = make_float4(0.f, 0.f, 0.f, 0.f);
    float4 aq = make_float4(0.f, 0.f, 0.f, 0.f);
    int s = w;
    for (; s + 8 < nseg; s += 16) {               // unroll 2 seg-steps
        const size_t o0 = ((size_t)s * DDOM + d) * FV + posIdx;
        const size_t o1 = ((size_t)(s + 8) * DDOM + d) * FV + posIdx;
        float4 p0 = P4[o0], q0 = Q4[o0];
        float4 p1 = P4[o1], q1 = Q4[o1];
        ap.x += p0.x + p1.x; ap.y += p0.y + p1.y;
        ap.z += p0.z + p1.z; ap.w += p0.w + p1.w;
        aq.x += q0.x + q1.x; aq.y += q0.y + q1.y;
        aq.z += q0.z + q1.z; aq.w += q0.w + q1.w;
    }
    for (; s < nseg; s += 8) {
        const size_t o = ((size_t)s * DDOM + d) * FV + posIdx;
        float4 p = P4[o], q = Q4[o];
        ap.x += p.x; ap.y += p.y; ap.z += p.z; ap.w += p.w;
        aq.x += q.x; aq.y += q.y; aq.z += q.z; aq.w += q.w;
    }
    smP[w][lane] = ap;
    smQ[w][lane] = aq;
    __syncthreads();

    // reduce count tree
    for (int off = 128; off > 0; off >>= 1) {
        if (tid < off) scnt[tid] += scnt[tid + off];
        __syncthreads();
    }
    const float c = (float)scnt[0];

    if (w == 0) {                                 // warp 0: cross-warp fold + math
        float4 s1 = smP[0][lane], s2 = smQ[0][lane];
#pragma unroll
        for (int ww = 1; ww < 8; ww++) {
            float4 p = smP[ww][lane], q = smQ[ww][lane];
            s1.x += p.x; s1.y += p.y; s1.z += p.z; s1.w += p.w;
            s2.x += q.x; s2.y += q.y; s2.z += q.z; s2.w += q.w;
        }
        const int o = d * FDIM + posIdx * 4;
        float4 A, Bv;
        if (c > 1.5f) {
            const float rc = 1.0f / c;
            float4 g  = *(const float4*)(gamma + o);
            float4 be = *(const float4*)(beta + o);
            float mx = s1.x * rc, my = s1.y * rc, mz = s1.z * rc, mw = s1.w * rc;
            float vx = fmaf(-mx, mx, s2.x * rc);
            float vy = fmaf(-my, my, s2.y * rc);
            float vz = fmaf(-mz, mz, s2.z * rc);
            float vw = fmaf(-mw, mw, s2.w * rc);
            A.x = g.x * rsqrtf(vx + EPSV);
            A.y = g.y * rsqrtf(vy + EPSV);
            A.z = g.z * rsqrtf(vz + EPSV);
            A.w = g.w * rsqrtf(vw + EPSV);
            Bv.x = fmaf(-mx, A.x, be.x);
            Bv.y = fmaf(-my, A.y, be.y);
            Bv.z = fmaf(-mz, A.z, be.z);
            Bv.w = fmaf(-mw, A.w, be.w);
        } else if (c > 0.5f) {   // single-sample domain: out = x
            A  = make_float4(1.f, 1.f, 1.f, 1.f);
            Bv = make_float4(0.f, 0.f, 0.f, 0.f);
        } else {                 // empty domain (unused)
            A  = make_float4(0.f, 0.f, 0.f, 0.f);
            Bv = make_float4(0.f, 0.f, 0.f, 0.f);
        }
        *(float4*)(g_A + o) = A;
        *(float4*)(g_B + o) = Bv;
    }
}

// ---------------- K3: out = A[d]*x + B[d] ----------------
__global__ __launch_bounds__(256)
void apply_k(const float4* __restrict__ x4, float4* __restrict__ o4, int n) {
    __shared__ int sd[RA];
    const int tid = threadIdx.x;
    const int r0  = blockIdx.x * RA;

    if (tid < RA) {
        const int r = r0 + tid;
        sd[tid] = (r < n) ? (int)g_ydom[r] : 0;
    }
    __syncthreads();

    const float4* A4 = (const float4*)g_A;
    const float4* B4 = (const float4*)g_B;

#pragma unroll
    for (int j = 0; j < RA; j += 4) {
        const int r = r0 + j;
        if (r + 3 < n) {
            const int d0 = sd[j], d1 = sd[j + 1], d2 = sd[j + 2], d3 = sd[j + 3];
            const float4* p = x4 + (size_t)r * FV + tid;
            float4 v0 = __ldcs(p);
            float4 v1 = __ldcs(p + FV);
            float4 v2 = __ldcs(p + 2 * FV);
            float4 v3 = __ldcs(p + 3 * FV);
            float4 a0 = __ldg(A4 + d0 * FV + tid);
            float4 b0 = __ldg(B4 + d0 * FV + tid);
            float4 a1 = __ldg(A4 + d1 * FV + tid);
            float4 b1 = __ldg(B4 + d1 * FV + tid);
            float4 a2 = __ldg(A4 + d2 * FV + tid);
            float4 b2 = __ldg(B4 + d2 * FV + tid);
            float4 a3 = __ldg(A4 + d3 * FV + tid);
            float4 b3 = __ldg(B4 + d3 * FV + tid);
            float4 w0, w1, w2, w3;
            w0.x = fmaf(v0.x, a0.x, b0.x); w0.y = fmaf(v0.y, a0.y, b0.y);
            w0.z = fmaf(v0.z, a0.z, b0.z); w0.w = fmaf(v0.w, a0.w, b0.w);
            w1.x = fmaf(v1.x, a1.x, b1.x); w1.y = fmaf(v1.y, a1.y, b1.y);
            w1.z = fmaf(v1.z, a1.z, b1.z); w1.w = fmaf(v1.w, a1.w, b1.w);
            w2.x = fmaf(v2.x, a2.x, b2.x); w2.y = fmaf(v2.y, a2.y, b2.y);
            w2.z = fmaf(v2.z, a2.z, b2.z); w2.w = fmaf(v2.w, a2.w, b2.w);
            w3.x = fmaf(v3.x, a3.x, b3.x); w3.y = fmaf(v3.y, a3.y, b3.y);
            w3.z = fmaf(v3.z, a3.z, b3.z); w3.w = fmaf(v3.w, a3.w, b3.w);
            float4* q = o4 + (size_t)r * FV + tid;
            __stcs(q,          w0);
            __stcs(q + FV,     w1);
            __stcs(q + 2 * FV, w2);
            __stcs(q + 3 * FV, w3);
        } else {
            for (int k = 0; k < 4; k++) {
                const int rr = r + k;
                if (rr >= n) break;
                const int dd = sd[j + k];
                float4 v = __ldcs(x4 + (size_t)rr * FV + tid);
                float4 a = __ldg(A4 + dd * FV + tid);
                float4 b = __ldg(B4 + dd * FV + tid);
                float4 w;
                w.x = fmaf(v.x, a.x, b.x); w.y = fmaf(v.y, a.y, b.y);
                w.z = fmaf(v.z, a.z, b.z); w.w = fmaf(v.w, a.w, b.w);
                __stcs(o4 + (size_t)rr * FV + tid, w);
            }
        }
    }
}

extern "C" void kernel_launch(void* const* d_in, const int* in_sizes, int n_in,
                              void* d_out, int out_size) {
    const float* x     = (const float*)d_in[0];
    const int*   y     = (const int*)d_in[1];
    const float* gamma = (const float*)d_in[2];
    const float* beta  = (const float*)d_in[3];
    float* out = (float*)d_out;

    const int n    = in_sizes[1];
    const int nseg = NSEG;                 // 296 = 2 exact waves
    const int rlo  = n / nseg;             // 55
    const int rem  = n - rlo * nseg;       // 104

    stats_k<<<nseg, 256>>>((const float4*)x, y, n, rlo, rem);
    finalize_k<<<DDOM * 8, 256>>>(gamma, beta, nseg);
    apply_k<<<(n + RA - 1) / RA, 256>>>((const float4*)x, (float4*)out, n);
}